// round 16
// baseline (speedup 1.0000x reference)
#include <cuda_runtime.h>
#include <cuda_fp16.h>
#include <cstdint>

// ---------------------------------------------------------------------------
// MixedGNN on GB300 — fp16 payload + register-dieted node path.
//   K0: global encoder (B=128 rows) -> g_HG, g_GM (global, L1-resident)
//   K1: i%2==0 -> fill block (128 thr x 16 e/t); i%2==1 -> node block
//       node: hg/gm via __ldg (broadcast), m/s accumulators split,
//       writes g_mh = fp16(relu(m)), g_base = s (fp32)
//   K2: aggregate: 4 thr/node, self row + deg neighbors via fp16 LDG.128,
//       fp32 acc, h = relu(s + m_self + sum), fused head. Resets g_cnt.
// ---------------------------------------------------------------------------

#define NMAX 200000
#define BMAX 1024
#define EMAX 6400000
#define HID  32
#define CAP  80      // bucket capacity; Poisson(32) overflow P ~ 1e-12

__device__ __align__(16) __half g_mh[(NMAX + 1) * HID]; // row NMAX stays zero
__device__ __align__(16) float g_base[NMAX * HID];      // s (fp32)
__device__ __align__(16) float g_HG[BMAX * HID];
__device__ __align__(16) float g_GM[BMAX * HID];
__device__ int g_cnt[NMAX];                      // zero-init; reset by k_aggr
__device__ __align__(16) int g_bkt[NMAX * CAP];

typedef unsigned long long u64;

__device__ __forceinline__ u64 splat2(float x) {
    u64 r;
    asm("mov.b64 %0, {%1, %1};" : "=l"(r) : "r"(__float_as_uint(x)));
    return r;
}
__device__ __forceinline__ void ffma2(u64& d, u64 a, u64 b) {
    asm("fma.rn.f32x2 %0, %1, %2, %0;" : "+l"(d) : "l"(a), "l"(b));
}
__device__ __forceinline__ float2 unpack2(u64 v) {
    unsigned lo, hi;
    asm("mov.b64 {%0, %1}, %2;" : "=r"(lo), "=r"(hi) : "l"(v));
    return make_float2(__uint_as_float(lo), __uint_as_float(hi));
}
__device__ __forceinline__ u64 pack2(float lo, float hi) {
    u64 r;
    asm("mov.b64 %0, {%1, %2};" : "=l"(r) : "r"(__float_as_uint(lo)), "r"(__float_as_uint(hi)));
    return r;
}
__device__ __forceinline__ unsigned h2u(__half2 h) {
    return *(unsigned*)&h;
}
__device__ __forceinline__ void addh8(float* a, uint4 v) {
    float2 f0 = __half22float2(*(__half2*)&v.x);
    float2 f1 = __half22float2(*(__half2*)&v.y);
    float2 f2 = __half22float2(*(__half2*)&v.z);
    float2 f3 = __half22float2(*(__half2*)&v.w);
    a[0] += f0.x; a[1] += f0.y; a[2] += f1.x; a[3] += f1.y;
    a[4] += f2.x; a[5] += f2.y; a[6] += f3.x; a[7] += f3.y;
}

// ---------------------------------------------------------------------------
// K0: global-graph encoder -> g_HG, g_GM.
// ---------------------------------------------------------------------------
__global__ void k_global(const float* __restrict__ xg,
                         const float* __restrict__ Wg, const float* __restrict__ bg,
                         const float* __restrict__ Wmix, const float* __restrict__ bmix,
                         int B) {
    int b = blockIdx.x * blockDim.x + threadIdx.x;
    if (b >= B) return;
    float x[8];
#pragma unroll
    for (int k = 0; k < 8; k++) x[k] = xg[b * 8 + k];
    float h[HID];
#pragma unroll
    for (int j = 0; j < HID; j++) {
        float a = bg[j];
#pragma unroll
        for (int k = 0; k < 8; k++) a = fmaf(x[k], Wg[k * HID + j], a);
        h[j] = fmaxf(a, 0.f);
        g_HG[b * HID + j] = h[j];
    }
#pragma unroll 4
    for (int j = 0; j < HID; j++) {
        float a = bmix[j];
#pragma unroll
        for (int k = 0; k < HID; k++) a = fmaf(h[k], Wmix[(32 + k) * HID + j], a);
        g_GM[b * HID + j] = a;
    }
}

// ---------------------------------------------------------------------------
// K1: interleaved fill/node, 1:1.
// ---------------------------------------------------------------------------
__global__ void __launch_bounds__(128)
k_node_fill(const float* __restrict__ x_local,
            const int* __restrict__ batch,
            const float* __restrict__ W_local, const float* __restrict__ b_local,
            const float* __restrict__ W_mix,
            const float* __restrict__ W_msg, const float* __restrict__ b_msg,
            const float* __restrict__ W_self, const float* __restrict__ b_self,
            const int* __restrict__ ei,
            int N, int E, int fillBlocks, int nodeBlocks) {
    int i = blockIdx.x;
    if ((i & 1) == 0) {
        // ---- fill path: 16 edges/thread ----
        int fillIdx = i >> 1;
        if (fillIdx >= fillBlocks) return;
        int e0 = (fillIdx * 128 + threadIdx.x) * 16;
        const int* dsts = ei + E;
        if (e0 + 15 < E) {
            int4 s0_ = *(const int4*)(ei + e0);
            int4 s1_ = *(const int4*)(ei + e0 + 4);
            int4 s2_ = *(const int4*)(ei + e0 + 8);
            int4 s3_ = *(const int4*)(ei + e0 + 12);
            int4 d0_ = *(const int4*)(dsts + e0);
            int4 d1_ = *(const int4*)(dsts + e0 + 4);
            int4 d2_ = *(const int4*)(dsts + e0 + 8);
            int4 d3_ = *(const int4*)(dsts + e0 + 12);
            int p0  = atomicAdd(&g_cnt[d0_.x], 1);
            int p1  = atomicAdd(&g_cnt[d0_.y], 1);
            int p2  = atomicAdd(&g_cnt[d0_.z], 1);
            int p3  = atomicAdd(&g_cnt[d0_.w], 1);
            int p4  = atomicAdd(&g_cnt[d1_.x], 1);
            int p5  = atomicAdd(&g_cnt[d1_.y], 1);
            int p6  = atomicAdd(&g_cnt[d1_.z], 1);
            int p7  = atomicAdd(&g_cnt[d1_.w], 1);
            int p8  = atomicAdd(&g_cnt[d2_.x], 1);
            int p9  = atomicAdd(&g_cnt[d2_.y], 1);
            int p10 = atomicAdd(&g_cnt[d2_.z], 1);
            int p11 = atomicAdd(&g_cnt[d2_.w], 1);
            int p12 = atomicAdd(&g_cnt[d3_.x], 1);
            int p13 = atomicAdd(&g_cnt[d3_.y], 1);
            int p14 = atomicAdd(&g_cnt[d3_.z], 1);
            int p15 = atomicAdd(&g_cnt[d3_.w], 1);
            g_bkt[d0_.x * CAP + p0]  = s0_.x;
            g_bkt[d0_.y * CAP + p1]  = s0_.y;
            g_bkt[d0_.z * CAP + p2]  = s0_.z;
            g_bkt[d0_.w * CAP + p3]  = s0_.w;
            g_bkt[d1_.x * CAP + p4]  = s1_.x;
            g_bkt[d1_.y * CAP + p5]  = s1_.y;
            g_bkt[d1_.z * CAP + p6]  = s1_.z;
            g_bkt[d1_.w * CAP + p7]  = s1_.w;
            g_bkt[d2_.x * CAP + p8]  = s2_.x;
            g_bkt[d2_.y * CAP + p9]  = s2_.y;
            g_bkt[d2_.z * CAP + p10] = s2_.z;
            g_bkt[d2_.w * CAP + p11] = s2_.w;
            g_bkt[d3_.x * CAP + p12] = s3_.x;
            g_bkt[d3_.y * CAP + p13] = s3_.y;
            g_bkt[d3_.z * CAP + p14] = s3_.z;
            g_bkt[d3_.w * CAP + p15] = s3_.w;
        } else {
            for (int e = e0; e < E; e++) {
                int d = dsts[e];
                int p = atomicAdd(&g_cnt[d], 1);
                g_bkt[d * CAP + p] = ei[e];
            }
        }
        return;
    }

    // ---- node path ----
    int nodeIdx = i >> 1;
    if (nodeIdx >= nodeBlocks) return;

    __shared__ __align__(16) float sWl[16 * HID];
    __shared__ __align__(16) float sWm1[HID * HID];
    __shared__ __align__(16) float sWm3[HID * HID];
    __shared__ __align__(16) float sWmsg[HID * HID];
    __shared__ __align__(16) float sWself[HID * HID];
    __shared__ __align__(16) float sb[3 * HID];

    for (int q = threadIdx.x; q < 16 * HID; q += 128) sWl[q] = W_local[q];
    for (int q = threadIdx.x; q < HID * HID; q += 128) {
        sWm1[q]   = W_mix[q];
        sWm3[q]   = W_mix[64 * HID + q];
        sWmsg[q]  = W_msg[q];
        sWself[q] = W_self[q];
    }
    for (int q = threadIdx.x; q < HID; q += 128) {
        sb[q]           = b_local[q];
        sb[HID + q]     = b_msg[q];
        sb[2 * HID + q] = b_self[q];
    }
    __syncthreads();

    int n = nodeIdx * 128 + threadIdx.x;
    if (n >= N) return;

    int b = batch[n];
    const float* hgp = g_HG + b * HID;   // warp-broadcast, L1-resident
    const float* gmp = g_GM + b * HID;

    float xl[16];
    {
        const float4* p = (const float4*)(x_local + (size_t)n * 16);
#pragma unroll
        for (int q = 0; q < 4; q++) {
            float4 v = p[q];
            xl[4 * q + 0] = v.x; xl[4 * q + 1] = v.y;
            xl[4 * q + 2] = v.z; xl[4 * q + 3] = v.w;
        }
    }

    // ---- hl = relu(xl @ W_local + b_local) ----
    float hl[HID];
    {
        u64 acc[16];
        const ulonglong2* bb = (const ulonglong2*)&sb[0];
#pragma unroll
        for (int q = 0; q < 8; q++) { ulonglong2 t2 = bb[q]; acc[2 * q] = t2.x; acc[2 * q + 1] = t2.y; }
#pragma unroll
        for (int k = 0; k < 16; k++) {
            u64 xs = splat2(xl[k]);
            const ulonglong2* w = (const ulonglong2*)&sWl[k * HID];
#pragma unroll
            for (int q = 0; q < 8; q++) {
                ulonglong2 ww = w[q];
                ffma2(acc[2 * q],     xs, ww.x);
                ffma2(acc[2 * q + 1], xs, ww.y);
            }
        }
#pragma unroll
        for (int q = 0; q < 16; q++) {
            float2 p = unpack2(acc[q]);
            hl[2 * q]     = fmaxf(p.x, 0.f);
            hl[2 * q + 1] = fmaxf(p.y, 0.f);
        }
    }

    // ---- h0 = relu(hl@Wm1 + (hl*hg)@Wm3 + gm), hg/gm streamed from L1 ----
    float h0[HID];
    {
        u64 acc[16];
        const float4* gm4 = (const float4*)gmp;
#pragma unroll
        for (int q = 0; q < 8; q++) {
            float4 v = __ldg(&gm4[q]);
            acc[2 * q]     = pack2(v.x, v.y);
            acc[2 * q + 1] = pack2(v.z, v.w);
        }
#pragma unroll 8
        for (int k = 0; k < HID; k++) {
            u64 s1 = splat2(hl[k]);
            u64 s2 = splat2(hl[k] * __ldg(&hgp[k]));
            const ulonglong2* w1 = (const ulonglong2*)&sWm1[k * HID];
            const ulonglong2* w3 = (const ulonglong2*)&sWm3[k * HID];
#pragma unroll
            for (int q = 0; q < 8; q++) {
                ulonglong2 ww1 = w1[q];
                ulonglong2 ww3 = w3[q];
                ffma2(acc[2 * q],     s1, ww1.x);
                ffma2(acc[2 * q + 1], s1, ww1.y);
                ffma2(acc[2 * q],     s2, ww3.x);
                ffma2(acc[2 * q + 1], s2, ww3.y);
            }
        }
#pragma unroll
        for (int q = 0; q < 16; q++) {
            float2 p = unpack2(acc[q]);
            h0[2 * q]     = fmaxf(p.x, 0.f);
            h0[2 * q + 1] = fmaxf(p.y, 0.f);
        }
    }

    // ---- phase 3a: m = relu(h0 @ W_msg + b_msg) -> fp16 g_mh ----
    {
        u64 am[16];
        const ulonglong2* bm = (const ulonglong2*)&sb[HID];
#pragma unroll
        for (int q = 0; q < 8; q++) { ulonglong2 t = bm[q]; am[2 * q] = t.x; am[2 * q + 1] = t.y; }
#pragma unroll 8
        for (int k = 0; k < HID; k++) {
            u64 s0 = splat2(h0[k]);
            const ulonglong2* wm = (const ulonglong2*)&sWmsg[k * HID];
#pragma unroll
            for (int q = 0; q < 8; q++) {
                ulonglong2 ww = wm[q];
                ffma2(am[2 * q],     s0, ww.x);
                ffma2(am[2 * q + 1], s0, ww.y);
            }
        }
        unsigned hx[16];
#pragma unroll
        for (int q = 0; q < 16; q++) {
            float2 p = unpack2(am[q]);
            hx[q] = h2u(__floats2half2_rn(fmaxf(p.x, 0.f), fmaxf(p.y, 0.f)));
        }
        uint4* pm = (uint4*)&g_mh[(size_t)n * HID];
#pragma unroll
        for (int q = 0; q < 4; q++)
            pm[q] = make_uint4(hx[4 * q], hx[4 * q + 1], hx[4 * q + 2], hx[4 * q + 3]);
    }

    // ---- phase 3b: s = h0 @ W_self + b_self -> fp32 g_base ----
    {
        u64 as_[16];
        const ulonglong2* bs = (const ulonglong2*)&sb[2 * HID];
#pragma unroll
        for (int q = 0; q < 8; q++) { ulonglong2 t = bs[q]; as_[2 * q] = t.x; as_[2 * q + 1] = t.y; }
#pragma unroll 8
        for (int k = 0; k < HID; k++) {
            u64 s0 = splat2(h0[k]);
            const ulonglong2* ws = (const ulonglong2*)&sWself[k * HID];
#pragma unroll
            for (int q = 0; q < 8; q++) {
                ulonglong2 ww = ws[q];
                ffma2(as_[2 * q],     s0, ww.x);
                ffma2(as_[2 * q + 1], s0, ww.y);
            }
        }
        float4* pb = (float4*)&g_base[(size_t)n * HID];
#pragma unroll
        for (int q = 0; q < 8; q++) {
            float2 p0 = unpack2(as_[2 * q]);
            float2 p1 = unpack2(as_[2 * q + 1]);
            pb[q] = make_float4(p0.x, p0.y, p1.x, p1.y);
        }
    }
}

// ---------------------------------------------------------------------------
// K2: aggregate, 4 threads/node (thread = 8 halves), fp32 acc, MLP-4.
//     acc = s + m_self(fp16) + sum(m_neighbors). Resets g_cnt.
// ---------------------------------------------------------------------------
__global__ void __launch_bounds__(256)
k_aggr(const float* __restrict__ W_out, const float* __restrict__ b_out,
       float* __restrict__ out, int N) {
    __shared__ float sw[HID * 2];
    __shared__ float sb2[2];
    if (threadIdx.x < HID * 2) sw[threadIdx.x] = W_out[threadIdx.x];
    if (threadIdx.x < 2) sb2[threadIdx.x] = b_out[threadIdx.x];
    __syncthreads();

    int t = blockIdx.x * 256 + threadIdx.x;
    int n = t >> 2;
    int p = t & 3;
    if (n >= N) return;

    int deg = __ldg(&g_cnt[n]);
    const int* bkt = g_bkt + n * CAP;
    const uint4* mh = (const uint4*)g_mh;   // row = 4 x uint4 (64B)

    float a0[8], a1[8];
    {
        const float4* bf = (const float4*)g_base;
        float4 bv0 = bf[(size_t)n * 8 + p * 2];
        float4 bv1 = bf[(size_t)n * 8 + p * 2 + 1];
        a0[0] = bv0.x; a0[1] = bv0.y; a0[2] = bv0.z; a0[3] = bv0.w;
        a0[4] = bv1.x; a0[5] = bv1.y; a0[6] = bv1.z; a0[7] = bv1.w;
#pragma unroll
        for (int q = 0; q < 8; q++) a1[q] = 0.f;
        // self loop message (fp16 row n)
        uint4 vs_ = __ldg(&mh[(unsigned)n * 4u + p]);
        addh8(a1, vs_);
    }

    for (int j = 0; j < deg; j += 4) {
        int4 s4 = *(const int4*)(bkt + j);
        int i0 = (j + 0 < deg) ? s4.x : NMAX;
        int i1 = (j + 1 < deg) ? s4.y : NMAX;
        int i2 = (j + 2 < deg) ? s4.z : NMAX;
        int i3 = (j + 3 < deg) ? s4.w : NMAX;
        uint4 v0 = __ldg(&mh[(unsigned)i0 * 4u + p]);
        uint4 v1 = __ldg(&mh[(unsigned)i1 * 4u + p]);
        uint4 v2 = __ldg(&mh[(unsigned)i2 * 4u + p]);
        uint4 v3 = __ldg(&mh[(unsigned)i3 * 4u + p]);
        addh8(a0, v0);
        addh8(a1, v1);
        addh8(a0, v2);
        addh8(a1, v3);
    }

    if (p == 0) g_cnt[n] = 0;   // reset for next replay (after read)

    int c = p * 8;
    float o0 = 0.f, o1 = 0.f;
#pragma unroll
    for (int q = 0; q < 8; q++) {
        float h = fmaxf(a0[q] + a1[q], 0.f);
        o0 = fmaf(h, sw[(c + q) * 2 + 0], o0);
        o1 = fmaf(h, sw[(c + q) * 2 + 1], o1);
    }
#pragma unroll
    for (int d = 2; d; d >>= 1) {
        o0 += __shfl_down_sync(0xffffffffu, o0, d, 4);
        o1 += __shfl_down_sync(0xffffffffu, o1, d, 4);
    }
    if (p == 0) ((float2*)out)[n] = make_float2(o0 + sb2[0], o1 + sb2[1]);
}

// ---------------------------------------------------------------------------
// Launch: [K0, K1, K2]
// ---------------------------------------------------------------------------
extern "C" void kernel_launch(void* const* d_in, const int* in_sizes, int n_in,
                              void* d_out, int out_size) {
    const float* x_local  = (const float*)d_in[0];
    const float* x_global = (const float*)d_in[1];
    const int*   batch    = (const int*)d_in[2];
    const int*   ei       = (const int*)d_in[3];
    const float* W_local  = (const float*)d_in[4];
    const float* b_local  = (const float*)d_in[5];
    const float* W_global = (const float*)d_in[6];
    const float* b_global = (const float*)d_in[7];
    const float* W_mix    = (const float*)d_in[8];
    const float* b_mix    = (const float*)d_in[9];
    const float* W_msg    = (const float*)d_in[10];
    const float* b_msg    = (const float*)d_in[11];
    const float* W_self   = (const float*)d_in[12];
    const float* b_self   = (const float*)d_in[13];
    const float* W_out    = (const float*)d_in[14];
    const float* b_out    = (const float*)d_in[15];
    float*       out      = (float*)d_out;

    int N = in_sizes[0] / 16;
    int B = in_sizes[1] / 8;
    int E = in_sizes[3] / 2;

    // K0: global encoder (tiny)
    k_global<<<(B + 127) / 128, 128>>>(x_global, W_global, b_global, W_mix, b_mix, B);

    // K1: interleaved fill + node
    int nodeBlocks = (N + 127) / 128;                 // 1563
    int fillBlocks = (E + 2047) / 2048;               // 3125
    int pairs = max(nodeBlocks, fillBlocks);
    k_node_fill<<<2 * pairs, 128>>>(
        x_local, batch, W_local, b_local, W_mix,
        W_msg, b_msg, W_self, b_self, ei, N, E, fillBlocks, nodeBlocks);

    // K2: aggregate + output head
    k_aggr<<<(N * 4 + 255) / 256, 256>>>(W_out, b_out, out, N);
}

// round 17
// speedup vs baseline: 1.1448x; 1.1448x over previous
#include <cuda_runtime.h>
#include <cuda_fp16.h>
#include <cstdint>

// ---------------------------------------------------------------------------
// MixedGNN on GB300 — fp16 payload + register-dieted node + parallel encoder.
//   K0: global encoder, 1 block per 8 batch rows (smem-staged HG -> GM)
//   K1: i%2==0 -> fill block (128 thr x 16 e/t); i%2==1 -> node block
//       node: hg/gm via __ldg (broadcast), m/s accumulators split,
//       writes g_mh = fp16(relu(m)), g_base = s (fp32)
//   K2: aggregate: 4 thr/node, self row + deg neighbors via fp16 LDG.128,
//       fp32 acc, h = relu(s + m_self + sum), fused head. Resets g_cnt.
// ---------------------------------------------------------------------------

#define NMAX 200000
#define BMAX 1024
#define EMAX 6400000
#define HID  32
#define CAP  80      // bucket capacity; Poisson(32) overflow P ~ 1e-12

__device__ __align__(16) __half g_mh[(NMAX + 1) * HID]; // row NMAX stays zero
__device__ __align__(16) float g_base[NMAX * HID];      // s (fp32)
__device__ __align__(16) float g_HG[BMAX * HID];
__device__ __align__(16) float g_GM[BMAX * HID];
__device__ int g_cnt[NMAX];                      // zero-init; reset by k_aggr
__device__ __align__(16) int g_bkt[NMAX * CAP];

typedef unsigned long long u64;

__device__ __forceinline__ u64 splat2(float x) {
    u64 r;
    asm("mov.b64 %0, {%1, %1};" : "=l"(r) : "r"(__float_as_uint(x)));
    return r;
}
__device__ __forceinline__ void ffma2(u64& d, u64 a, u64 b) {
    asm("fma.rn.f32x2 %0, %1, %2, %0;" : "+l"(d) : "l"(a), "l"(b));
}
__device__ __forceinline__ float2 unpack2(u64 v) {
    unsigned lo, hi;
    asm("mov.b64 {%0, %1}, %2;" : "=r"(lo), "=r"(hi) : "l"(v));
    return make_float2(__uint_as_float(lo), __uint_as_float(hi));
}
__device__ __forceinline__ u64 pack2(float lo, float hi) {
    u64 r;
    asm("mov.b64 %0, {%1, %2};" : "=l"(r) : "r"(__float_as_uint(lo)), "r"(__float_as_uint(hi)));
    return r;
}
__device__ __forceinline__ unsigned h2u(__half2 h) {
    return *(unsigned*)&h;
}
__device__ __forceinline__ void addh8(float* a, uint4 v) {
    float2 f0 = __half22float2(*(__half2*)&v.x);
    float2 f1 = __half22float2(*(__half2*)&v.y);
    float2 f2 = __half22float2(*(__half2*)&v.z);
    float2 f3 = __half22float2(*(__half2*)&v.w);
    a[0] += f0.x; a[1] += f0.y; a[2] += f1.x; a[3] += f1.y;
    a[4] += f2.x; a[5] += f2.y; a[6] += f3.x; a[7] += f3.y;
}

// ---------------------------------------------------------------------------
// K0: global-graph encoder, 8 batch rows per 256-thread block.
//     thread = (b_local = tid/32, j = tid%32).
// ---------------------------------------------------------------------------
__global__ void __launch_bounds__(256)
k_global(const float* __restrict__ xg,
         const float* __restrict__ Wg, const float* __restrict__ bg,
         const float* __restrict__ Wmix, const float* __restrict__ bmix,
         int B) {
    __shared__ float sHG[8 * HID];
    int bl = threadIdx.x >> 5;           // 0..7
    int j  = threadIdx.x & 31;
    int b  = blockIdx.x * 8 + bl;
    bool act = (b < B);

    float h = 0.f;
    if (act) {
        float a = bg[j];
#pragma unroll
        for (int k = 0; k < 8; k++) a = fmaf(xg[b * 8 + k], Wg[k * HID + j], a);
        h = fmaxf(a, 0.f);
        g_HG[b * HID + j] = h;
    }
    sHG[bl * HID + j] = h;
    __syncthreads();

    if (act) {
        float a = bmix[j];
#pragma unroll 8
        for (int k = 0; k < HID; k++)
            a = fmaf(sHG[bl * HID + k], Wmix[(32 + k) * HID + j], a);
        g_GM[b * HID + j] = a;
    }
}

// ---------------------------------------------------------------------------
// K1: interleaved fill/node, 1:1.
// ---------------------------------------------------------------------------
__global__ void __launch_bounds__(128)
k_node_fill(const float* __restrict__ x_local,
            const int* __restrict__ batch,
            const float* __restrict__ W_local, const float* __restrict__ b_local,
            const float* __restrict__ W_mix,
            const float* __restrict__ W_msg, const float* __restrict__ b_msg,
            const float* __restrict__ W_self, const float* __restrict__ b_self,
            const int* __restrict__ ei,
            int N, int E, int fillBlocks, int nodeBlocks) {
    int i = blockIdx.x;
    if ((i & 1) == 0) {
        // ---- fill path: 16 edges/thread ----
        int fillIdx = i >> 1;
        if (fillIdx >= fillBlocks) return;
        int e0 = (fillIdx * 128 + threadIdx.x) * 16;
        const int* dsts = ei + E;
        if (e0 + 15 < E) {
            int4 s0_ = *(const int4*)(ei + e0);
            int4 s1_ = *(const int4*)(ei + e0 + 4);
            int4 s2_ = *(const int4*)(ei + e0 + 8);
            int4 s3_ = *(const int4*)(ei + e0 + 12);
            int4 d0_ = *(const int4*)(dsts + e0);
            int4 d1_ = *(const int4*)(dsts + e0 + 4);
            int4 d2_ = *(const int4*)(dsts + e0 + 8);
            int4 d3_ = *(const int4*)(dsts + e0 + 12);
            int p0  = atomicAdd(&g_cnt[d0_.x], 1);
            int p1  = atomicAdd(&g_cnt[d0_.y], 1);
            int p2  = atomicAdd(&g_cnt[d0_.z], 1);
            int p3  = atomicAdd(&g_cnt[d0_.w], 1);
            int p4  = atomicAdd(&g_cnt[d1_.x], 1);
            int p5  = atomicAdd(&g_cnt[d1_.y], 1);
            int p6  = atomicAdd(&g_cnt[d1_.z], 1);
            int p7  = atomicAdd(&g_cnt[d1_.w], 1);
            int p8  = atomicAdd(&g_cnt[d2_.x], 1);
            int p9  = atomicAdd(&g_cnt[d2_.y], 1);
            int p10 = atomicAdd(&g_cnt[d2_.z], 1);
            int p11 = atomicAdd(&g_cnt[d2_.w], 1);
            int p12 = atomicAdd(&g_cnt[d3_.x], 1);
            int p13 = atomicAdd(&g_cnt[d3_.y], 1);
            int p14 = atomicAdd(&g_cnt[d3_.z], 1);
            int p15 = atomicAdd(&g_cnt[d3_.w], 1);
            g_bkt[d0_.x * CAP + p0]  = s0_.x;
            g_bkt[d0_.y * CAP + p1]  = s0_.y;
            g_bkt[d0_.z * CAP + p2]  = s0_.z;
            g_bkt[d0_.w * CAP + p3]  = s0_.w;
            g_bkt[d1_.x * CAP + p4]  = s1_.x;
            g_bkt[d1_.y * CAP + p5]  = s1_.y;
            g_bkt[d1_.z * CAP + p6]  = s1_.z;
            g_bkt[d1_.w * CAP + p7]  = s1_.w;
            g_bkt[d2_.x * CAP + p8]  = s2_.x;
            g_bkt[d2_.y * CAP + p9]  = s2_.y;
            g_bkt[d2_.z * CAP + p10] = s2_.z;
            g_bkt[d2_.w * CAP + p11] = s2_.w;
            g_bkt[d3_.x * CAP + p12] = s3_.x;
            g_bkt[d3_.y * CAP + p13] = s3_.y;
            g_bkt[d3_.z * CAP + p14] = s3_.z;
            g_bkt[d3_.w * CAP + p15] = s3_.w;
        } else {
            for (int e = e0; e < E; e++) {
                int d = dsts[e];
                int p = atomicAdd(&g_cnt[d], 1);
                g_bkt[d * CAP + p] = ei[e];
            }
        }
        return;
    }

    // ---- node path ----
    int nodeIdx = i >> 1;
    if (nodeIdx >= nodeBlocks) return;

    __shared__ __align__(16) float sWl[16 * HID];
    __shared__ __align__(16) float sWm1[HID * HID];
    __shared__ __align__(16) float sWm3[HID * HID];
    __shared__ __align__(16) float sWmsg[HID * HID];
    __shared__ __align__(16) float sWself[HID * HID];
    __shared__ __align__(16) float sb[3 * HID];

    for (int q = threadIdx.x; q < 16 * HID; q += 128) sWl[q] = W_local[q];
    for (int q = threadIdx.x; q < HID * HID; q += 128) {
        sWm1[q]   = W_mix[q];
        sWm3[q]   = W_mix[64 * HID + q];
        sWmsg[q]  = W_msg[q];
        sWself[q] = W_self[q];
    }
    for (int q = threadIdx.x; q < HID; q += 128) {
        sb[q]           = b_local[q];
        sb[HID + q]     = b_msg[q];
        sb[2 * HID + q] = b_self[q];
    }
    __syncthreads();

    int n = nodeIdx * 128 + threadIdx.x;
    if (n >= N) return;

    int b = batch[n];
    const float* hgp = g_HG + b * HID;   // warp-broadcast, L1-resident
    const float* gmp = g_GM + b * HID;

    float xl[16];
    {
        const float4* p = (const float4*)(x_local + (size_t)n * 16);
#pragma unroll
        for (int q = 0; q < 4; q++) {
            float4 v = p[q];
            xl[4 * q + 0] = v.x; xl[4 * q + 1] = v.y;
            xl[4 * q + 2] = v.z; xl[4 * q + 3] = v.w;
        }
    }

    // ---- hl = relu(xl @ W_local + b_local) ----
    float hl[HID];
    {
        u64 acc[16];
        const ulonglong2* bb = (const ulonglong2*)&sb[0];
#pragma unroll
        for (int q = 0; q < 8; q++) { ulonglong2 t2 = bb[q]; acc[2 * q] = t2.x; acc[2 * q + 1] = t2.y; }
#pragma unroll
        for (int k = 0; k < 16; k++) {
            u64 xs = splat2(xl[k]);
            const ulonglong2* w = (const ulonglong2*)&sWl[k * HID];
#pragma unroll
            for (int q = 0; q < 8; q++) {
                ulonglong2 ww = w[q];
                ffma2(acc[2 * q],     xs, ww.x);
                ffma2(acc[2 * q + 1], xs, ww.y);
            }
        }
#pragma unroll
        for (int q = 0; q < 16; q++) {
            float2 p = unpack2(acc[q]);
            hl[2 * q]     = fmaxf(p.x, 0.f);
            hl[2 * q + 1] = fmaxf(p.y, 0.f);
        }
    }

    // ---- h0 = relu(hl@Wm1 + (hl*hg)@Wm3 + gm), hg/gm streamed from L1 ----
    float h0[HID];
    {
        u64 acc[16];
        const float4* gm4 = (const float4*)gmp;
#pragma unroll
        for (int q = 0; q < 8; q++) {
            float4 v = __ldg(&gm4[q]);
            acc[2 * q]     = pack2(v.x, v.y);
            acc[2 * q + 1] = pack2(v.z, v.w);
        }
#pragma unroll 8
        for (int k = 0; k < HID; k++) {
            u64 s1 = splat2(hl[k]);
            u64 s2 = splat2(hl[k] * __ldg(&hgp[k]));
            const ulonglong2* w1 = (const ulonglong2*)&sWm1[k * HID];
            const ulonglong2* w3 = (const ulonglong2*)&sWm3[k * HID];
#pragma unroll
            for (int q = 0; q < 8; q++) {
                ulonglong2 ww1 = w1[q];
                ulonglong2 ww3 = w3[q];
                ffma2(acc[2 * q],     s1, ww1.x);
                ffma2(acc[2 * q + 1], s1, ww1.y);
                ffma2(acc[2 * q],     s2, ww3.x);
                ffma2(acc[2 * q + 1], s2, ww3.y);
            }
        }
#pragma unroll
        for (int q = 0; q < 16; q++) {
            float2 p = unpack2(acc[q]);
            h0[2 * q]     = fmaxf(p.x, 0.f);
            h0[2 * q + 1] = fmaxf(p.y, 0.f);
        }
    }

    // ---- phase 3a: m = relu(h0 @ W_msg + b_msg) -> fp16 g_mh ----
    {
        u64 am[16];
        const ulonglong2* bm = (const ulonglong2*)&sb[HID];
#pragma unroll
        for (int q = 0; q < 8; q++) { ulonglong2 t = bm[q]; am[2 * q] = t.x; am[2 * q + 1] = t.y; }
#pragma unroll 8
        for (int k = 0; k < HID; k++) {
            u64 s0 = splat2(h0[k]);
            const ulonglong2* wm = (const ulonglong2*)&sWmsg[k * HID];
#pragma unroll
            for (int q = 0; q < 8; q++) {
                ulonglong2 ww = wm[q];
                ffma2(am[2 * q],     s0, ww.x);
                ffma2(am[2 * q + 1], s0, ww.y);
            }
        }
        unsigned hx[16];
#pragma unroll
        for (int q = 0; q < 16; q++) {
            float2 p = unpack2(am[q]);
            hx[q] = h2u(__floats2half2_rn(fmaxf(p.x, 0.f), fmaxf(p.y, 0.f)));
        }
        uint4* pm = (uint4*)&g_mh[(size_t)n * HID];
#pragma unroll
        for (int q = 0; q < 4; q++)
            pm[q] = make_uint4(hx[4 * q], hx[4 * q + 1], hx[4 * q + 2], hx[4 * q + 3]);
    }

    // ---- phase 3b: s = h0 @ W_self + b_self -> fp32 g_base ----
    {
        u64 as_[16];
        const ulonglong2* bs = (const ulonglong2*)&sb[2 * HID];
#pragma unroll
        for (int q = 0; q < 8; q++) { ulonglong2 t = bs[q]; as_[2 * q] = t.x; as_[2 * q + 1] = t.y; }
#pragma unroll 8
        for (int k = 0; k < HID; k++) {
            u64 s0 = splat2(h0[k]);
            const ulonglong2* ws = (const ulonglong2*)&sWself[k * HID];
#pragma unroll
            for (int q = 0; q < 8; q++) {
                ulonglong2 ww = ws[q];
                ffma2(as_[2 * q],     s0, ww.x);
                ffma2(as_[2 * q + 1], s0, ww.y);
            }
        }
        float4* pb = (float4*)&g_base[(size_t)n * HID];
#pragma unroll
        for (int q = 0; q < 8; q++) {
            float2 p0 = unpack2(as_[2 * q]);
            float2 p1 = unpack2(as_[2 * q + 1]);
            pb[q] = make_float4(p0.x, p0.y, p1.x, p1.y);
        }
    }
}

// ---------------------------------------------------------------------------
// K2: aggregate, 4 threads/node (thread = 8 halves), fp32 acc, MLP-4.
//     acc = s + m_self(fp16) + sum(m_neighbors). Resets g_cnt.
// ---------------------------------------------------------------------------
__global__ void __launch_bounds__(256)
k_aggr(const float* __restrict__ W_out, const float* __restrict__ b_out,
       float* __restrict__ out, int N) {
    __shared__ float sw[HID * 2];
    __shared__ float sb2[2];
    if (threadIdx.x < HID * 2) sw[threadIdx.x] = W_out[threadIdx.x];
    if (threadIdx.x < 2) sb2[threadIdx.x] = b_out[threadIdx.x];
    __syncthreads();

    int t = blockIdx.x * 256 + threadIdx.x;
    int n = t >> 2;
    int p = t & 3;
    if (n >= N) return;

    int deg = __ldg(&g_cnt[n]);
    const int* bkt = g_bkt + n * CAP;
    const uint4* mh = (const uint4*)g_mh;   // row = 4 x uint4 (64B)

    float a0[8], a1[8];
    {
        const float4* bf = (const float4*)g_base;
        float4 bv0 = bf[(size_t)n * 8 + p * 2];
        float4 bv1 = bf[(size_t)n * 8 + p * 2 + 1];
        a0[0] = bv0.x; a0[1] = bv0.y; a0[2] = bv0.z; a0[3] = bv0.w;
        a0[4] = bv1.x; a0[5] = bv1.y; a0[6] = bv1.z; a0[7] = bv1.w;
#pragma unroll
        for (int q = 0; q < 8; q++) a1[q] = 0.f;
        // self loop message (fp16 row n)
        uint4 vs_ = __ldg(&mh[(unsigned)n * 4u + p]);
        addh8(a1, vs_);
    }

    for (int j = 0; j < deg; j += 4) {
        int4 s4 = *(const int4*)(bkt + j);
        int i0 = (j + 0 < deg) ? s4.x : NMAX;
        int i1 = (j + 1 < deg) ? s4.y : NMAX;
        int i2 = (j + 2 < deg) ? s4.z : NMAX;
        int i3 = (j + 3 < deg) ? s4.w : NMAX;
        uint4 v0 = __ldg(&mh[(unsigned)i0 * 4u + p]);
        uint4 v1 = __ldg(&mh[(unsigned)i1 * 4u + p]);
        uint4 v2 = __ldg(&mh[(unsigned)i2 * 4u + p]);
        uint4 v3 = __ldg(&mh[(unsigned)i3 * 4u + p]);
        addh8(a0, v0);
        addh8(a1, v1);
        addh8(a0, v2);
        addh8(a1, v3);
    }

    if (p == 0) g_cnt[n] = 0;   // reset for next replay (after read)

    int c = p * 8;
    float o0 = 0.f, o1 = 0.f;
#pragma unroll
    for (int q = 0; q < 8; q++) {
        float h = fmaxf(a0[q] + a1[q], 0.f);
        o0 = fmaf(h, sw[(c + q) * 2 + 0], o0);
        o1 = fmaf(h, sw[(c + q) * 2 + 1], o1);
    }
#pragma unroll
    for (int d = 2; d; d >>= 1) {
        o0 += __shfl_down_sync(0xffffffffu, o0, d, 4);
        o1 += __shfl_down_sync(0xffffffffu, o1, d, 4);
    }
    if (p == 0) ((float2*)out)[n] = make_float2(o0 + sb2[0], o1 + sb2[1]);
}

// ---------------------------------------------------------------------------
// Launch: [K0, K1, K2]
// ---------------------------------------------------------------------------
extern "C" void kernel_launch(void* const* d_in, const int* in_sizes, int n_in,
                              void* d_out, int out_size) {
    const float* x_local  = (const float*)d_in[0];
    const float* x_global = (const float*)d_in[1];
    const int*   batch    = (const int*)d_in[2];
    const int*   ei       = (const int*)d_in[3];
    const float* W_local  = (const float*)d_in[4];
    const float* b_local  = (const float*)d_in[5];
    const float* W_global = (const float*)d_in[6];
    const float* b_global = (const float*)d_in[7];
    const float* W_mix    = (const float*)d_in[8];
    const float* b_mix    = (const float*)d_in[9];
    const float* W_msg    = (const float*)d_in[10];
    const float* b_msg    = (const float*)d_in[11];
    const float* W_self   = (const float*)d_in[12];
    const float* b_self   = (const float*)d_in[13];
    const float* W_out    = (const float*)d_in[14];
    const float* b_out    = (const float*)d_in[15];
    float*       out      = (float*)d_out;

    int N = in_sizes[0] / 16;
    int B = in_sizes[1] / 8;
    int E = in_sizes[3] / 2;

    // K0: global encoder (parallel: 8 batch rows per block)
    k_global<<<(B + 7) / 8, 256>>>(x_global, W_global, b_global, W_mix, b_mix, B);

    // K1: interleaved fill + node
    int nodeBlocks = (N + 127) / 128;                 // 1563
    int fillBlocks = (E + 2047) / 2048;               // 3125
    int pairs = max(nodeBlocks, fillBlocks);
    k_node_fill<<<2 * pairs, 128>>>(
        x_local, batch, W_local, b_local, W_mix,
        W_msg, b_msg, W_self, b_self, ei, N, E, fillBlocks, nodeBlocks);

    // K2: aggregate + output head
    k_aggr<<<(N * 4 + 255) / 256, 256>>>(W_out, b_out, out, N);
}